// round 11
// baseline (speedup 1.0000x reference)
#include <cuda_runtime.h>
#include <cuda_fp16.h>
#include <math.h>

#define N_ATOMS   8000
#define N_PAIRS   80000
#define NF        32          // nf_in == nf_out
#define ND        16          // n_dist
#define NC        4           // n_comp
#define SPAN      (ND * NF)   // 512 halves per atom row
#define HARD_CUT  6.5f
#define GN_EPS    1e-5f

// scratch
__device__ __half g_projh[N_ATOMS * SPAN];        // proj[j][o][d] fp16 (8.2 MB)
__device__ __align__(16) float g_sense[N_PAIRS * ND];  // sense[p][d] (5.1 MB)

union U2  { unsigned long long u; float2 f; };
union F4U { float4 f4; unsigned long long u[2]; };

__device__ __forceinline__ unsigned long long ffma2(unsigned long long a,
                                                    unsigned long long b,
                                                    unsigned long long c) {
    unsigned long long d;
    asm("fma.rn.f32x2 %0, %1, %2, %3;" : "=l"(d) : "l"(a), "l"(b), "l"(c));
    return d;
}

// ---------------- K0: sense[p][d] -------------------------------------------
__global__ void sense_kernel(const float* __restrict__ dist,
                             const float* __restrict__ mu,
                             const float* __restrict__ sigma) {
    int t = blockIdx.x * blockDim.x + threadIdx.x;
    if (t >= N_PAIRS * ND) return;
    int p = t >> 4;
    int d = t & 15;
    float dp   = dist[p];
    float invd = 1.0f / dp;
    float z    = (invd - mu[d]) / sigma[d];
    float base = __expf(-0.5f * z * z);
    float c    = __cosf(0.24166097335f * dp);     // 0.5*pi/6.5
    float cut  = (dp < HARD_CUT) ? c * c : 0.0f;
    g_sense[t] = base * cut;
}

// ---------------- K1: proj[j][o][d] = sum_f feat[j,f] * W[d,o,f] ------------
#define APB 16
__global__ __launch_bounds__(512) void proj_kernel(
        const float* __restrict__ feat,
        const float* __restrict__ intw) {
    int t = threadIdx.x;
    int o = t >> 4, d = t & 15;

    float w[NF];
    const float4* wp = reinterpret_cast<const float4*>(intw + (d * NF + o) * NF);
#pragma unroll
    for (int k = 0; k < NF / 4; k++) {
        float4 v = wp[k];
        w[4 * k + 0] = v.x; w[4 * k + 1] = v.y;
        w[4 * k + 2] = v.z; w[4 * k + 3] = v.w;
    }

    __shared__ __align__(16) float fshT[NF][20];
    __shared__ __align__(16) __half sstage[APB][SPAN];
    int a0 = blockIdx.x * APB;
    {
        int a = t >> 5, f = t & 31;
        fshT[f][a] = feat[(a0 + a) * NF + f];
    }
    __syncthreads();

    unsigned long long acc[8];
#pragma unroll
    for (int k = 0; k < 8; k++) acc[k] = 0ull;

#pragma unroll
    for (int f = 0; f < NF; f++) {
        U2 w2; w2.f = make_float2(w[f], w[f]);
        const float4* row = reinterpret_cast<const float4*>(fshT[f]);
#pragma unroll
        for (int q = 0; q < 4; q++) {
            F4U v; v.f4 = row[q];
            acc[2 * q + 0] = ffma2(w2.u, v.u[0], acc[2 * q + 0]);
            acc[2 * q + 1] = ffma2(w2.u, v.u[1], acc[2 * q + 1]);
        }
    }

    int pos = o * ND + d;
#pragma unroll
    for (int k = 0; k < 8; k++) {
        U2 a; a.u = acc[k];
        sstage[2 * k + 0][pos] = __float2half_rn(a.f.x);
        sstage[2 * k + 1][pos] = __float2half_rn(a.f.y);
    }
    __syncthreads();

    const uint4* s4 = reinterpret_cast<const uint4*>(sstage);
    uint4* g4 = reinterpret_cast<uint4*>(g_projh) + a0 * (SPAN / 8);
#pragma unroll
    for (int k = 0; k < 2; k++)
        g4[k * 512 + t] = s4[k * 512 + t];
}

// per-pair in-lane dot: h = sum_d sense[d]*proj[d]; sense uniform across lanes
__device__ __forceinline__ float pair_dot(uint4 v0, uint4 v1,
                                          float4 s0, float4 s1,
                                          float4 s2, float4 s3) {
    const __half2* h0 = reinterpret_cast<const __half2*>(&v0);
    const __half2* h1 = reinterpret_cast<const __half2*>(&v1);
    float h = 0.f;
    float2 c;
    c = __half22float2(h0[0]); h = fmaf(s0.x, c.x, h); h = fmaf(s0.y, c.y, h);
    c = __half22float2(h0[1]); h = fmaf(s0.z, c.x, h); h = fmaf(s0.w, c.y, h);
    c = __half22float2(h0[2]); h = fmaf(s1.x, c.x, h); h = fmaf(s1.y, c.y, h);
    c = __half22float2(h0[3]); h = fmaf(s1.z, c.x, h); h = fmaf(s1.w, c.y, h);
    c = __half22float2(h1[0]); h = fmaf(s2.x, c.x, h); h = fmaf(s2.y, c.y, h);
    c = __half22float2(h1[1]); h = fmaf(s2.z, c.x, h); h = fmaf(s2.w, c.y, h);
    c = __half22float2(h1[2]); h = fmaf(s3.x, c.x, h); h = fmaf(s3.y, c.y, h);
    c = __half22float2(h1[3]); h = fmaf(s3.z, c.x, h); h = fmaf(s3.w, c.y, h);
    return h;
}

// ---------------- K2: per-atom warp — pair loop + invariants + GN + mix -----
__global__ __launch_bounds__(256) void atom_kernel(
        const float* __restrict__ feat,
        const float* __restrict__ rhat,        // (P,4)
        const int*   __restrict__ pair_first,  // sorted
        const int*   __restrict__ pair_second,
        const float* __restrict__ selfw,       // (32,32) [o][f]
        const float* __restrict__ selfb,
        const float* __restrict__ mixw,        // (64,32) k*32+oo, k=o*2+g
        const float* __restrict__ gnw,         // (64) [g*32+o]
        const float* __restrict__ gnb,
        float* __restrict__ out) {
    __shared__ float swsh[NF * NF];
    __shared__ float xn_sh[8][64];

    for (int i = threadIdx.x; i < NF * NF; i += 256)
        swsh[i] = selfw[(i & 31) * NF + (i >> 5)];
    __syncthreads();

    int warp = threadIdx.x >> 5;
    int lane = threadIdx.x & 31;
    int a = blockIdx.x * 8 + warp;

    // segment search: lanes 0/1
    int target = a + (lane & 1);
    int lo = 0, hi = N_PAIRS;
    while (lo < hi) {
        int mid = (lo + hi) >> 1;
        if (pair_first[mid] < target) lo = mid + 1; else hi = mid;
    }
    int p0 = __shfl_sync(0xffffffffu, lo, 0);
    int p1 = __shfl_sync(0xffffffffu, lo, 1);

    float tf0 = 0.f, tf1 = 0.f, tf2 = 0.f, tf3 = 0.f;
    const float4* sb = reinterpret_cast<const float4*>(g_sense);

    int p = p0;
    for (; p + 1 < p1; p += 2) {
        int ja = pair_second[p];
        int jb = pair_second[p + 1];
        const uint4* pa = reinterpret_cast<const uint4*>(g_projh + ja * SPAN);
        const uint4* pb = reinterpret_cast<const uint4*>(g_projh + jb * SPAN);
        uint4 va0 = pa[2 * lane + 0], va1 = pa[2 * lane + 1];
        uint4 vb0 = pb[2 * lane + 0], vb1 = pb[2 * lane + 1];
        float4 sa0 = sb[p * 4 + 0], sa1 = sb[p * 4 + 1];
        float4 sa2 = sb[p * 4 + 2], sa3 = sb[p * 4 + 3];
        float4 sb0 = sb[p * 4 + 4], sb1 = sb[p * 4 + 5];
        float4 sb2 = sb[p * 4 + 6], sb3 = sb[p * 4 + 7];
        const float4 ra = *reinterpret_cast<const float4*>(rhat + p * NC);
        const float4 rb = *reinterpret_cast<const float4*>(rhat + (p + 1) * NC);

        float hA = pair_dot(va0, va1, sa0, sa1, sa2, sa3);
        float hB = pair_dot(vb0, vb1, sb0, sb1, sb2, sb3);

        tf0 = fmaf(ra.x, hA, tf0); tf0 = fmaf(rb.x, hB, tf0);
        tf1 = fmaf(ra.y, hA, tf1); tf1 = fmaf(rb.y, hB, tf1);
        tf2 = fmaf(ra.z, hA, tf2); tf2 = fmaf(rb.z, hB, tf2);
        tf3 = fmaf(ra.w, hA, tf3); tf3 = fmaf(rb.w, hB, tf3);
    }
    if (p < p1) {
        int j = pair_second[p];
        const uint4* pr = reinterpret_cast<const uint4*>(g_projh + j * SPAN);
        uint4 v0 = pr[2 * lane + 0], v1 = pr[2 * lane + 1];
        float4 s0 = sb[p * 4 + 0], s1 = sb[p * 4 + 1];
        float4 s2 = sb[p * 4 + 2], s3 = sb[p * 4 + 3];
        const float4 r = *reinterpret_cast<const float4*>(rhat + p * NC);
        float h = pair_dot(v0, v1, s0, s1, s2, s3);
        tf0 = fmaf(r.x, h, tf0);
        tf1 = fmaf(r.y, h, tf1);
        tf2 = fmaf(r.z, h, tf2);
        tf3 = fmaf(r.w, h, tf3);
    }

    // invariants
    float inv0 = tf0;
    float inv1 = tf1 * tf1 + tf2 * tf2 + tf3 * tf3;

    // GroupNorm across lanes
    float xn0, xn1;
    {
        float s = inv0, sq = inv0 * inv0;
#pragma unroll
        for (int m = 16; m; m >>= 1) {
            s  += __shfl_xor_sync(0xffffffffu, s,  m);
            sq += __shfl_xor_sync(0xffffffffu, sq, m);
        }
        float mean = s * (1.0f / 32.0f);
        float var  = sq * (1.0f / 32.0f) - mean * mean;
        xn0 = (inv0 - mean) * rsqrtf(var + GN_EPS) * gnw[lane] + gnb[lane];
    }
    {
        float s = inv1, sq = inv1 * inv1;
#pragma unroll
        for (int m = 16; m; m >>= 1) {
            s  += __shfl_xor_sync(0xffffffffu, s,  m);
            sq += __shfl_xor_sync(0xffffffffu, sq, m);
        }
        float mean = s * (1.0f / 32.0f);
        float var  = sq * (1.0f / 32.0f) - mean * mean;
        xn1 = (inv1 - mean) * rsqrtf(var + GN_EPS) * gnw[NF + lane] + gnb[NF + lane];
    }
    xn_sh[warp][lane * 2 + 0] = xn0;   // k = o*2 + g
    xn_sh[warp][lane * 2 + 1] = xn1;
    __syncwarp();

    float m = 0.f;
#pragma unroll
    for (int k = 0; k < 2 * NF; k++)
        m = fmaf(xn_sh[warp][k], mixw[k * NF + lane], m);

    float sp = selfb[lane];
    const float* fa = feat + a * NF;
#pragma unroll
    for (int f = 0; f < NF; f++)
        sp = fmaf(fa[f], swsh[f * NF + lane], sp);

    out[a * NF + lane] = m + sp;
}

// ---------------- launch ----------------------------------------------------
extern "C" void kernel_launch(void* const* d_in, const int* in_sizes, int n_in,
                              void* d_out, int out_size) {
    const float* in_features    = (const float*)d_in[0];
    const float* tensor_rhats   = (const float*)d_in[1];
    const float* dist_pairs     = (const float*)d_in[2];
    const float* int_weights    = (const float*)d_in[3];
    const float* selfint_w      = (const float*)d_in[4];
    const float* selfint_b      = (const float*)d_in[5];
    const float* mixing_weights = (const float*)d_in[6];
    const float* gn_weight      = (const float*)d_in[7];
    const float* gn_bias        = (const float*)d_in[8];
    const float* sens_mu        = (const float*)d_in[9];
    const float* sens_sigma     = (const float*)d_in[10];
    const int*   pair_first     = (const int*)d_in[11];
    const int*   pair_second    = (const int*)d_in[12];
    float* out = (float*)d_out;

    sense_kernel<<<(N_PAIRS * ND + 255) / 256, 256>>>(dist_pairs, sens_mu, sens_sigma);
    proj_kernel<<<N_ATOMS / APB, 512>>>(in_features, int_weights);
    atom_kernel<<<N_ATOMS / 8, 256>>>(in_features, tensor_rhats,
                                      pair_first, pair_second,
                                      selfint_w, selfint_b, mixing_weights,
                                      gn_weight, gn_bias, out);
}

// round 12
// speedup vs baseline: 1.1393x; 1.1393x over previous
#include <cuda_runtime.h>
#include <cuda_fp16.h>
#include <math.h>

#define N_ATOMS   8000
#define N_PAIRS   80000
#define NF        32          // nf_in == nf_out
#define ND        16          // n_dist
#define NC        4           // n_comp
#define SPAN      (ND * NF)   // 512 halves per atom row
#define HARD_CUT  6.5f
#define GN_EPS    1e-5f

// scratch
__device__ __half g_projh[N_ATOMS * SPAN];   // proj[j][o][d] fp16 (8.2 MB)
__device__ float  g_h[N_PAIRS * NF];         // h[p][o] (10.2 MB)

union U2  { unsigned long long u; float2 f; };
union F4U { float4 f4; unsigned long long u[2]; };

__device__ __forceinline__ unsigned long long ffma2(unsigned long long a,
                                                    unsigned long long b,
                                                    unsigned long long c) {
    unsigned long long d;
    asm("fma.rn.f32x2 %0, %1, %2, %3;" : "=l"(d) : "l"(a), "l"(b), "l"(c));
    return d;
}

// ---------------- K1: proj[j][o][d] = sum_f feat[j,f] * W[d,o,f] ------------
#define APB 16
__global__ __launch_bounds__(512) void proj_kernel(
        const float* __restrict__ feat,
        const float* __restrict__ intw) {
    int t = threadIdx.x;
    int o = t >> 4, d = t & 15;

    float w[NF];
    const float4* wp = reinterpret_cast<const float4*>(intw + (d * NF + o) * NF);
#pragma unroll
    for (int k = 0; k < NF / 4; k++) {
        float4 v = wp[k];
        w[4 * k + 0] = v.x; w[4 * k + 1] = v.y;
        w[4 * k + 2] = v.z; w[4 * k + 3] = v.w;
    }

    __shared__ __align__(16) float fshT[NF][20];
    __shared__ __align__(16) __half sstage[APB][SPAN];
    int a0 = blockIdx.x * APB;
    {
        int a = t >> 5, f = t & 31;
        fshT[f][a] = feat[(a0 + a) * NF + f];
    }
    __syncthreads();

    unsigned long long acc[8];
#pragma unroll
    for (int k = 0; k < 8; k++) acc[k] = 0ull;

#pragma unroll
    for (int f = 0; f < NF; f++) {
        U2 w2; w2.f = make_float2(w[f], w[f]);
        const float4* row = reinterpret_cast<const float4*>(fshT[f]);
#pragma unroll
        for (int q = 0; q < 4; q++) {
            F4U v; v.f4 = row[q];
            acc[2 * q + 0] = ffma2(w2.u, v.u[0], acc[2 * q + 0]);
            acc[2 * q + 1] = ffma2(w2.u, v.u[1], acc[2 * q + 1]);
        }
    }

    int pos = o * ND + d;                    // o-major position
#pragma unroll
    for (int k = 0; k < 8; k++) {
        U2 a; a.u = acc[k];
        sstage[2 * k + 0][pos] = __float2half_rn(a.f.x);
        sstage[2 * k + 1][pos] = __float2half_rn(a.f.y);
    }
    __syncthreads();

    const uint4* s4 = reinterpret_cast<const uint4*>(sstage);
    uint4* g4 = reinterpret_cast<uint4*>(g_projh) + a0 * (SPAN / 8);
#pragma unroll
    for (int k = 0; k < 2; k++)
        g4[k * 512 + t] = s4[k * 512 + t];
}

// in-lane 16-d dot with uniform sense
__device__ __forceinline__ float pair_dot(uint4 v0, uint4 v1,
                                          float4 s0, float4 s1,
                                          float4 s2, float4 s3) {
    const __half2* h0 = reinterpret_cast<const __half2*>(&v0);
    const __half2* h1 = reinterpret_cast<const __half2*>(&v1);
    float h = 0.f;
    float2 c;
    c = __half22float2(h0[0]); h = fmaf(s0.x, c.x, h); h = fmaf(s0.y, c.y, h);
    c = __half22float2(h0[1]); h = fmaf(s0.z, c.x, h); h = fmaf(s0.w, c.y, h);
    c = __half22float2(h0[2]); h = fmaf(s1.x, c.x, h); h = fmaf(s1.y, c.y, h);
    c = __half22float2(h0[3]); h = fmaf(s1.z, c.x, h); h = fmaf(s1.w, c.y, h);
    c = __half22float2(h1[0]); h = fmaf(s2.x, c.x, h); h = fmaf(s2.y, c.y, h);
    c = __half22float2(h1[1]); h = fmaf(s2.z, c.x, h); h = fmaf(s2.w, c.y, h);
    c = __half22float2(h1[2]); h = fmaf(s3.x, c.x, h); h = fmaf(s3.y, c.y, h);
    c = __half22float2(h1[3]); h = fmaf(s3.z, c.x, h); h = fmaf(s3.w, c.y, h);
    return h;
}

// ---------------- K2: h[p,o] = sum_d sense[p,d] * proj[j_p,o,d] -------------
// One warp per pair (80K warps). Sense in lanes<16 -> smem -> broadcast LDS.
__global__ __launch_bounds__(256) void hpair_kernel(
        const float* __restrict__ dist,
        const float* __restrict__ mu,
        const float* __restrict__ sigma,
        const int* __restrict__ pair_second) {
    __shared__ __align__(16) float ssh[8][16];
    int warp = threadIdx.x >> 5;
    int lane = threadIdx.x & 31;
    int p = blockIdx.x * 8 + warp;            // grid = N_PAIRS/8 exact

    // issue proj loads first (overlap with sense math)
    int j = pair_second[p];                   // uniform
    const uint4* pr = reinterpret_cast<const uint4*>(g_projh + j * SPAN);
    uint4 v0 = pr[2 * lane + 0];
    uint4 v1 = pr[2 * lane + 1];

    float dp = dist[p];                       // uniform broadcast
    if (lane < ND) {
        float invd = __fdividef(1.0f, dp);
        float z    = __fdividef(invd - mu[lane], sigma[lane]);
        float base = __expf(-0.5f * z * z);
        float c    = __cosf(0.24166097335f * dp);   // 0.5*pi/6.5
        float cut  = (dp < HARD_CUT) ? c * c : 0.0f;
        ssh[warp][lane] = base * cut;
    }
    __syncwarp();
    const float4* sr = reinterpret_cast<const float4*>(ssh[warp]);
    float4 s0 = sr[0], s1 = sr[1], s2 = sr[2], s3 = sr[3];

    g_h[p * NF + lane] = pair_dot(v0, v1, s0, s1, s2, s3);
}

// ---------------- K3: per-atom warp — h loop + invariants + GN + mix --------
__global__ __launch_bounds__(256) void atom_kernel(
        const float* __restrict__ feat,
        const float* __restrict__ rhat,        // (P,4)
        const int*   __restrict__ pair_first,  // sorted
        const float* __restrict__ selfw,       // (32,32) [o][f]
        const float* __restrict__ selfb,
        const float* __restrict__ mixw,        // (64,32) k*32+oo, k=o*2+g
        const float* __restrict__ gnw,         // (64) [g*32+o]
        const float* __restrict__ gnb,
        float* __restrict__ out) {
    __shared__ float swsh[NF * NF];
    __shared__ float xn_sh[8][64];

    for (int i = threadIdx.x; i < NF * NF; i += 256)
        swsh[i] = selfw[(i & 31) * NF + (i >> 5)];
    __syncthreads();

    int warp = threadIdx.x >> 5;
    int lane = threadIdx.x & 31;
    int a = blockIdx.x * 8 + warp;

    // segment search: lanes 0/1 find lower_bound(a), lower_bound(a+1)
    int target = a + (lane & 1);
    int lo = 0, hi = N_PAIRS;
    while (lo < hi) {
        int mid = (lo + hi) >> 1;
        if (pair_first[mid] < target) lo = mid + 1; else hi = mid;
    }
    int p0 = __shfl_sync(0xffffffffu, lo, 0);
    int p1 = __shfl_sync(0xffffffffu, lo, 1);

    float tf0 = 0.f, tf1 = 0.f, tf2 = 0.f, tf3 = 0.f;
    int p = p0;
    for (; p + 1 < p1; p += 2) {
        float ha = g_h[p * NF + lane];
        float hb = g_h[(p + 1) * NF + lane];
        const float4 ra = *reinterpret_cast<const float4*>(rhat + p * NC);
        const float4 rb = *reinterpret_cast<const float4*>(rhat + (p + 1) * NC);
        tf0 = fmaf(ra.x, ha, tf0); tf0 = fmaf(rb.x, hb, tf0);
        tf1 = fmaf(ra.y, ha, tf1); tf1 = fmaf(rb.y, hb, tf1);
        tf2 = fmaf(ra.z, ha, tf2); tf2 = fmaf(rb.z, hb, tf2);
        tf3 = fmaf(ra.w, ha, tf3); tf3 = fmaf(rb.w, hb, tf3);
    }
    if (p < p1) {
        float ha = g_h[p * NF + lane];
        const float4 ra = *reinterpret_cast<const float4*>(rhat + p * NC);
        tf0 = fmaf(ra.x, ha, tf0);
        tf1 = fmaf(ra.y, ha, tf1);
        tf2 = fmaf(ra.z, ha, tf2);
        tf3 = fmaf(ra.w, ha, tf3);
    }

    // invariants
    float inv0 = tf0;
    float inv1 = tf1 * tf1 + tf2 * tf2 + tf3 * tf3;

    // GroupNorm across lanes
    float xn0, xn1;
    {
        float s = inv0, sq = inv0 * inv0;
#pragma unroll
        for (int m = 16; m; m >>= 1) {
            s  += __shfl_xor_sync(0xffffffffu, s,  m);
            sq += __shfl_xor_sync(0xffffffffu, sq, m);
        }
        float mean = s * (1.0f / 32.0f);
        float var  = sq * (1.0f / 32.0f) - mean * mean;
        xn0 = (inv0 - mean) * rsqrtf(var + GN_EPS) * gnw[lane] + gnb[lane];
    }
    {
        float s = inv1, sq = inv1 * inv1;
#pragma unroll
        for (int m = 16; m; m >>= 1) {
            s  += __shfl_xor_sync(0xffffffffu, s,  m);
            sq += __shfl_xor_sync(0xffffffffu, sq, m);
        }
        float mean = s * (1.0f / 32.0f);
        float var  = sq * (1.0f / 32.0f) - mean * mean;
        xn1 = (inv1 - mean) * rsqrtf(var + GN_EPS) * gnw[NF + lane] + gnb[NF + lane];
    }
    xn_sh[warp][lane * 2 + 0] = xn0;   // k = o*2 + g
    xn_sh[warp][lane * 2 + 1] = xn1;
    __syncwarp();

    float m = 0.f;
#pragma unroll
    for (int k = 0; k < 2 * NF; k++)
        m = fmaf(xn_sh[warp][k], mixw[k * NF + lane], m);

    float sp = selfb[lane];
    const float* fa = feat + a * NF;
#pragma unroll
    for (int f = 0; f < NF; f++)
        sp = fmaf(fa[f], swsh[f * NF + lane], sp);

    out[a * NF + lane] = m + sp;
}

// ---------------- launch ----------------------------------------------------
extern "C" void kernel_launch(void* const* d_in, const int* in_sizes, int n_in,
                              void* d_out, int out_size) {
    const float* in_features    = (const float*)d_in[0];
    const float* tensor_rhats   = (const float*)d_in[1];
    const float* dist_pairs     = (const float*)d_in[2];
    const float* int_weights    = (const float*)d_in[3];
    const float* selfint_w      = (const float*)d_in[4];
    const float* selfint_b      = (const float*)d_in[5];
    const float* mixing_weights = (const float*)d_in[6];
    const float* gn_weight      = (const float*)d_in[7];
    const float* gn_bias        = (const float*)d_in[8];
    const float* sens_mu        = (const float*)d_in[9];
    const float* sens_sigma     = (const float*)d_in[10];
    const int*   pair_first     = (const int*)d_in[11];
    const int*   pair_second    = (const int*)d_in[12];
    float* out = (float*)d_out;

    proj_kernel<<<N_ATOMS / APB, 512>>>(in_features, int_weights);
    hpair_kernel<<<N_PAIRS / 8, 256>>>(dist_pairs, sens_mu, sens_sigma, pair_second);
    atom_kernel<<<N_ATOMS / 8, 256>>>(in_features, tensor_rhats, pair_first,
                                      selfint_w, selfint_b, mixing_weights,
                                      gn_weight, gn_bias, out);
}

// round 13
// speedup vs baseline: 1.2384x; 1.0870x over previous
#include <cuda_runtime.h>
#include <cuda_fp16.h>
#include <math.h>

#define N_ATOMS   8000
#define N_PAIRS   80000
#define NF        32          // nf_in == nf_out
#define ND        16          // n_dist
#define NC        4           // n_comp
#define SPAN      (ND * NF)   // 512 halves per atom row
#define HARD_CUT  6.5f
#define GN_EPS    1e-5f

// scratch
__device__ __half g_projh[N_ATOMS * SPAN];   // proj[j][o][d] fp16 (8.2 MB)
__device__ float  g_h[N_PAIRS * NF];         // h[p][o] (10.2 MB)

union U2  { unsigned long long u; float2 f; };
union F4U { float4 f4; unsigned long long u[2]; };

__device__ __forceinline__ unsigned long long ffma2(unsigned long long a,
                                                    unsigned long long b,
                                                    unsigned long long c) {
    unsigned long long d;
    asm("fma.rn.f32x2 %0, %1, %2, %3;" : "=l"(d) : "l"(a), "l"(b), "l"(c));
    return d;
}

// ---------------- K1: proj[j][o][d] = sum_f feat[j,f] * W[d,o,f] ------------
// thread t -> (o = t>>4, d = t&15), i.e. weight row r(t) = (t&15)*32 + (t>>4).
// Weights staged via smem: coalesced LDG -> conflict-free STS/LDS.
#define APB 16
__global__ __launch_bounds__(512) void proj_kernel(
        const float* __restrict__ feat,
        const float* __restrict__ intw) {
    int t = threadIdx.x;
    int o = t >> 4, d = t & 15;

    __shared__ float wsm[NF][513];                 // wsm[f][t'] (65.7 KB)
    __shared__ __align__(16) float fshT[NF][20];
    __shared__ __align__(16) __half sstage[APB][SPAN];

    int a0 = blockIdx.x * APB;
    {
        int a = t >> 5, f = t & 31;
        fshT[f][a] = feat[(a0 + a) * NF + f];
    }
    // coalesced weight load: i = k*512 + t covers all 512*32 floats
#pragma unroll
    for (int k = 0; k < 32; k++) {
        int i = k * 512 + t;
        int row = i >> 5, f = i & 31;
        // dest thread t' with r(t') = row:  t' = (row&31)*16 + (row>>5)
        wsm[f][(row & 31) * 16 + (row >> 5)] = intw[i];
    }
    __syncthreads();

    float w[NF];
#pragma unroll
    for (int f = 0; f < NF; f++) w[f] = wsm[f][t];  // conflict-free

    unsigned long long acc[8];
#pragma unroll
    for (int k = 0; k < 8; k++) acc[k] = 0ull;

#pragma unroll
    for (int f = 0; f < NF; f++) {
        U2 w2; w2.f = make_float2(w[f], w[f]);
        const float4* row = reinterpret_cast<const float4*>(fshT[f]);
#pragma unroll
        for (int q = 0; q < 4; q++) {
            F4U v; v.f4 = row[q];                   // broadcast LDS.128
            acc[2 * q + 0] = ffma2(w2.u, v.u[0], acc[2 * q + 0]);
            acc[2 * q + 1] = ffma2(w2.u, v.u[1], acc[2 * q + 1]);
        }
    }

    int pos = o * ND + d;                           // o-major position = t
#pragma unroll
    for (int k = 0; k < 8; k++) {
        U2 a; a.u = acc[k];
        sstage[2 * k + 0][pos] = __float2half_rn(a.f.x);
        sstage[2 * k + 1][pos] = __float2half_rn(a.f.y);
    }
    __syncthreads();

    const uint4* s4 = reinterpret_cast<const uint4*>(sstage);
    uint4* g4 = reinterpret_cast<uint4*>(g_projh) + a0 * (SPAN / 8);
#pragma unroll
    for (int k = 0; k < 2; k++)
        g4[k * 512 + t] = s4[k * 512 + t];
}

// in-lane 16-d dot with uniform sense
__device__ __forceinline__ float pair_dot(uint4 v0, uint4 v1,
                                          float4 s0, float4 s1,
                                          float4 s2, float4 s3) {
    const __half2* h0 = reinterpret_cast<const __half2*>(&v0);
    const __half2* h1 = reinterpret_cast<const __half2*>(&v1);
    float h = 0.f;
    float2 c;
    c = __half22float2(h0[0]); h = fmaf(s0.x, c.x, h); h = fmaf(s0.y, c.y, h);
    c = __half22float2(h0[1]); h = fmaf(s0.z, c.x, h); h = fmaf(s0.w, c.y, h);
    c = __half22float2(h0[2]); h = fmaf(s1.x, c.x, h); h = fmaf(s1.y, c.y, h);
    c = __half22float2(h0[3]); h = fmaf(s1.z, c.x, h); h = fmaf(s1.w, c.y, h);
    c = __half22float2(h1[0]); h = fmaf(s2.x, c.x, h); h = fmaf(s2.y, c.y, h);
    c = __half22float2(h1[1]); h = fmaf(s2.z, c.x, h); h = fmaf(s2.w, c.y, h);
    c = __half22float2(h1[2]); h = fmaf(s3.x, c.x, h); h = fmaf(s3.y, c.y, h);
    c = __half22float2(h1[3]); h = fmaf(s3.z, c.x, h); h = fmaf(s3.w, c.y, h);
    return h;
}

// ---------------- K2: h[p,o] = sum_d sense[p,d] * proj[j_p,o,d] -------------
__global__ __launch_bounds__(256) void hpair_kernel(
        const float* __restrict__ dist,
        const float* __restrict__ mu,
        const float* __restrict__ sigma,
        const int* __restrict__ pair_second) {
    __shared__ __align__(16) float ssh[8][16];
    int warp = threadIdx.x >> 5;
    int lane = threadIdx.x & 31;
    int p = blockIdx.x * 8 + warp;            // grid = N_PAIRS/8 exact

    int j = pair_second[p];                   // uniform
    const uint4* pr = reinterpret_cast<const uint4*>(g_projh + j * SPAN);
    uint4 v0 = pr[2 * lane + 0];
    uint4 v1 = pr[2 * lane + 1];

    float dp = dist[p];                       // uniform broadcast
    if (lane < ND) {
        float invd = __fdividef(1.0f, dp);
        float z    = __fdividef(invd - mu[lane], sigma[lane]);
        float base = __expf(-0.5f * z * z);
        float c    = __cosf(0.24166097335f * dp);   // 0.5*pi/6.5
        float cut  = (dp < HARD_CUT) ? c * c : 0.0f;
        ssh[warp][lane] = base * cut;
    }
    __syncwarp();
    const float4* sr = reinterpret_cast<const float4*>(ssh[warp]);
    float4 s0 = sr[0], s1 = sr[1], s2 = sr[2], s3 = sr[3];

    g_h[p * NF + lane] = pair_dot(v0, v1, s0, s1, s2, s3);
}

// ---------------- K3: per-atom warp — h loop + invariants + GN + mix --------
__global__ __launch_bounds__(256) void atom_kernel(
        const float* __restrict__ feat,
        const float* __restrict__ rhat,        // (P,4)
        const int*   __restrict__ pair_first,  // sorted
        const float* __restrict__ selfw,       // (32,32) [o][f]
        const float* __restrict__ selfb,
        const float* __restrict__ mixw,        // (64,32) k*32+oo, k=o*2+g
        const float* __restrict__ gnw,         // (64) [g*32+o]
        const float* __restrict__ gnb,
        float* __restrict__ out) {
    __shared__ float swsh[NF * NF];
    __shared__ float xn_sh[8][64];

    for (int i = threadIdx.x; i < NF * NF; i += 256)
        swsh[i] = selfw[(i & 31) * NF + (i >> 5)];
    __syncthreads();

    int warp = threadIdx.x >> 5;
    int lane = threadIdx.x & 31;
    int a = blockIdx.x * 8 + warp;

    // segment search: lanes 0/1
    int target = a + (lane & 1);
    int lo = 0, hi = N_PAIRS;
    while (lo < hi) {
        int mid = (lo + hi) >> 1;
        if (pair_first[mid] < target) lo = mid + 1; else hi = mid;
    }
    int p0 = __shfl_sync(0xffffffffu, lo, 0);
    int p1 = __shfl_sync(0xffffffffu, lo, 1);

    float tf0 = 0.f, tf1 = 0.f, tf2 = 0.f, tf3 = 0.f;
    int p = p0;
    for (; p + 1 < p1; p += 2) {
        float ha = g_h[p * NF + lane];
        float hb = g_h[(p + 1) * NF + lane];
        const float4 ra = *reinterpret_cast<const float4*>(rhat + p * NC);
        const float4 rb = *reinterpret_cast<const float4*>(rhat + (p + 1) * NC);
        tf0 = fmaf(ra.x, ha, tf0); tf0 = fmaf(rb.x, hb, tf0);
        tf1 = fmaf(ra.y, ha, tf1); tf1 = fmaf(rb.y, hb, tf1);
        tf2 = fmaf(ra.z, ha, tf2); tf2 = fmaf(rb.z, hb, tf2);
        tf3 = fmaf(ra.w, ha, tf3); tf3 = fmaf(rb.w, hb, tf3);
    }
    if (p < p1) {
        float ha = g_h[p * NF + lane];
        const float4 ra = *reinterpret_cast<const float4*>(rhat + p * NC);
        tf0 = fmaf(ra.x, ha, tf0);
        tf1 = fmaf(ra.y, ha, tf1);
        tf2 = fmaf(ra.z, ha, tf2);
        tf3 = fmaf(ra.w, ha, tf3);
    }

    // invariants
    float inv0 = tf0;
    float inv1 = tf1 * tf1 + tf2 * tf2 + tf3 * tf3;

    // GroupNorm across lanes
    float xn0, xn1;
    {
        float s = inv0, sq = inv0 * inv0;
#pragma unroll
        for (int m = 16; m; m >>= 1) {
            s  += __shfl_xor_sync(0xffffffffu, s,  m);
            sq += __shfl_xor_sync(0xffffffffu, sq, m);
        }
        float mean = s * (1.0f / 32.0f);
        float var  = sq * (1.0f / 32.0f) - mean * mean;
        xn0 = (inv0 - mean) * rsqrtf(var + GN_EPS) * gnw[lane] + gnb[lane];
    }
    {
        float s = inv1, sq = inv1 * inv1;
#pragma unroll
        for (int m = 16; m; m >>= 1) {
            s  += __shfl_xor_sync(0xffffffffu, s,  m);
            sq += __shfl_xor_sync(0xffffffffu, sq, m);
        }
        float mean = s * (1.0f / 32.0f);
        float var  = sq * (1.0f / 32.0f) - mean * mean;
        xn1 = (inv1 - mean) * rsqrtf(var + GN_EPS) * gnw[NF + lane] + gnb[NF + lane];
    }
    xn_sh[warp][lane * 2 + 0] = xn0;   // k = o*2 + g
    xn_sh[warp][lane * 2 + 1] = xn1;
    __syncwarp();

    float m = 0.f;
#pragma unroll
    for (int k = 0; k < 2 * NF; k++)
        m = fmaf(xn_sh[warp][k], mixw[k * NF + lane], m);

    float sp = selfb[lane];
    const float* fa = feat + a * NF;
#pragma unroll
    for (int f = 0; f < NF; f++)
        sp = fmaf(fa[f], swsh[f * NF + lane], sp);

    out[a * NF + lane] = m + sp;
}

// ---------------- launch ----------------------------------------------------
extern "C" void kernel_launch(void* const* d_in, const int* in_sizes, int n_in,
                              void* d_out, int out_size) {
    const float* in_features    = (const float*)d_in[0];
    const float* tensor_rhats   = (const float*)d_in[1];
    const float* dist_pairs     = (const float*)d_in[2];
    const float* int_weights    = (const float*)d_in[3];
    const float* selfint_w      = (const float*)d_in[4];
    const float* selfint_b      = (const float*)d_in[5];
    const float* mixing_weights = (const float*)d_in[6];
    const float* gn_weight      = (const float*)d_in[7];
    const float* gn_bias        = (const float*)d_in[8];
    const float* sens_mu        = (const float*)d_in[9];
    const float* sens_sigma     = (const float*)d_in[10];
    const int*   pair_first     = (const int*)d_in[11];
    const int*   pair_second    = (const int*)d_in[12];
    float* out = (float*)d_out;

    proj_kernel<<<N_ATOMS / APB, 512>>>(in_features, int_weights);
    hpair_kernel<<<N_PAIRS / 8, 256>>>(dist_pairs, sens_mu, sens_sigma, pair_second);
    atom_kernel<<<N_ATOMS / 8, 256>>>(in_features, tensor_rhats, pair_first,
                                      selfint_w, selfint_b, mixing_weights,
                                      gn_weight, gn_bias, out);
}

// round 15
// speedup vs baseline: 1.2934x; 1.0444x over previous
#include <cuda_runtime.h>
#include <cuda_fp16.h>
#include <math.h>

#define N_ATOMS   8000
#define N_PAIRS   80000
#define NF        32          // nf_in == nf_out
#define ND        16          // n_dist
#define NC        4           // n_comp
#define SPAN      (ND * NF)   // 512 halves per atom row
#define HARD_CUT  6.5f
#define GN_EPS    1e-5f

// scratch
__device__ __half g_projh[N_ATOMS * SPAN];   // proj[j][o][d] fp16 (8.2 MB)
__device__ __half g_hh[N_PAIRS * NF];        // h[p][o] fp16 (5.1 MB)

union U2  { unsigned long long u; float2 f; };
union F4U { float4 f4; unsigned long long u[2]; };

__device__ __forceinline__ unsigned long long ffma2(unsigned long long a,
                                                    unsigned long long b,
                                                    unsigned long long c) {
    unsigned long long d;
    asm("fma.rn.f32x2 %0, %1, %2, %3;" : "=l"(d) : "l"(a), "l"(b), "l"(c));
    return d;
}

// ---------------- K1: proj[j][o][d] = sum_f feat[j,f] * W[d,o,f] ------------
// thread t -> (o = t>>4, d = t&15). 32 atoms/block in two 16-atom chunks;
// weights staged once per block (coalesced LDG -> conflict-free STS/LDS).
#define APB 32
__global__ __launch_bounds__(512) void proj_kernel(
        const float* __restrict__ feat,
        const float* __restrict__ intw) {
    int t = threadIdx.x;
    int o = t >> 4, d = t & 15;

    __shared__ float wsm[NF][513];                 // wsm[f][t'] (65.7 KB)
    __shared__ __align__(16) float fshT[NF][40];   // 32 atoms transposed (5 KB)
    __shared__ __align__(16) __half sstage[16][SPAN];  // 16 KB

    int a0 = blockIdx.x * APB;
    for (int i = t; i < NF * APB; i += 512) {
        int a = i >> 5, f = i & 31;
        fshT[f][a] = feat[(a0 + a) * NF + f];      // coalesced
    }
    // coalesced weight load: i = k*512 + t covers all 512*32 floats
#pragma unroll
    for (int k = 0; k < 32; k++) {
        int i = k * 512 + t;
        int row = i >> 5, f = i & 31;
        wsm[f][(row & 31) * 16 + (row >> 5)] = intw[i];
    }
    __syncthreads();

    float w[NF];
#pragma unroll
    for (int f = 0; f < NF; f++) w[f] = wsm[f][t]; // conflict-free

    int pos = o * ND + d;                          // o-major position
#pragma unroll 1
    for (int c = 0; c < 2; c++) {
        unsigned long long acc[8];
#pragma unroll
        for (int k = 0; k < 8; k++) acc[k] = 0ull;

#pragma unroll
        for (int f = 0; f < NF; f++) {
            U2 w2; w2.f = make_float2(w[f], w[f]);
            const float4* row = reinterpret_cast<const float4*>(fshT[f]);
#pragma unroll
            for (int q = 0; q < 4; q++) {
                F4U v; v.f4 = row[c * 4 + q];      // broadcast LDS.128
                acc[2 * q + 0] = ffma2(w2.u, v.u[0], acc[2 * q + 0]);
                acc[2 * q + 1] = ffma2(w2.u, v.u[1], acc[2 * q + 1]);
            }
        }

        if (c) __syncthreads();                    // prev writeout done
#pragma unroll
        for (int k = 0; k < 8; k++) {
            U2 a; a.u = acc[k];
            sstage[2 * k + 0][pos] = __float2half_rn(a.f.x);
            sstage[2 * k + 1][pos] = __float2half_rn(a.f.y);
        }
        __syncthreads();

        const uint4* s4 = reinterpret_cast<const uint4*>(sstage);
        uint4* g4 = reinterpret_cast<uint4*>(g_projh)
                  + (a0 + c * 16) * (SPAN / 8);
#pragma unroll
        for (int k = 0; k < 2; k++)
            g4[k * 512 + t] = s4[k * 512 + t];
    }
}

// in-lane 16-d dot with uniform sense
__device__ __forceinline__ float pair_dot(uint4 v0, uint4 v1,
                                          float4 s0, float4 s1,
                                          float4 s2, float4 s3) {
    const __half2* h0 = reinterpret_cast<const __half2*>(&v0);
    const __half2* h1 = reinterpret_cast<const __half2*>(&v1);
    float h = 0.f;
    float2 c;
    c = __half22float2(h0[0]); h = fmaf(s0.x, c.x, h); h = fmaf(s0.y, c.y, h);
    c = __half22float2(h0[1]); h = fmaf(s0.z, c.x, h); h = fmaf(s0.w, c.y, h);
    c = __half22float2(h0[2]); h = fmaf(s1.x, c.x, h); h = fmaf(s1.y, c.y, h);
    c = __half22float2(h0[3]); h = fmaf(s1.z, c.x, h); h = fmaf(s1.w, c.y, h);
    c = __half22float2(h1[0]); h = fmaf(s2.x, c.x, h); h = fmaf(s2.y, c.y, h);
    c = __half22float2(h1[1]); h = fmaf(s2.z, c.x, h); h = fmaf(s2.w, c.y, h);
    c = __half22float2(h1[2]); h = fmaf(s3.x, c.x, h); h = fmaf(s3.y, c.y, h);
    c = __half22float2(h1[3]); h = fmaf(s3.z, c.x, h); h = fmaf(s3.w, c.y, h);
    return h;
}

// ---------------- K2: h[p,o] = sum_d sense[p,d] * proj[j_p,o,d] -------------
__global__ __launch_bounds__(256) void hpair_kernel(
        const float* __restrict__ dist,
        const float* __restrict__ mu,
        const float* __restrict__ sigma,
        const int* __restrict__ pair_second) {
    __shared__ __align__(16) float ssh[8][16];
    int warp = threadIdx.x >> 5;
    int lane = threadIdx.x & 31;
    int p = blockIdx.x * 8 + warp;            // grid = N_PAIRS/8 exact

    int j = pair_second[p];                   // uniform
    const uint4* pr = reinterpret_cast<const uint4*>(g_projh + j * SPAN);
    uint4 v0 = pr[2 * lane + 0];
    uint4 v1 = pr[2 * lane + 1];

    float dp = dist[p];                       // uniform broadcast
    if (lane < ND) {
        float invd = __fdividef(1.0f, dp);
        float z    = __fdividef(invd - mu[lane], sigma[lane]);
        float base = __expf(-0.5f * z * z);
        float c    = __cosf(0.24166097335f * dp);   // 0.5*pi/6.5
        float cut  = (dp < HARD_CUT) ? c * c : 0.0f;
        ssh[warp][lane] = base * cut;
    }
    __syncwarp();
    const float4* sr = reinterpret_cast<const float4*>(ssh[warp]);
    float4 s0 = sr[0], s1 = sr[1], s2 = sr[2], s3 = sr[3];

    g_hh[p * NF + lane] = __float2half_rn(pair_dot(v0, v1, s0, s1, s2, s3));
}

// ---------------- K3: per-atom warp — h loop + invariants + GN + mix --------
__global__ __launch_bounds__(256) void atom_kernel(
        const float* __restrict__ feat,
        const float* __restrict__ rhat,        // (P,4)
        const int*   __restrict__ pair_first,  // sorted
        const float* __restrict__ selfw,       // (32,32) [o][f]
        const float* __restrict__ selfb,
        const float* __restrict__ mixw,        // (64,32) k*32+oo, k=o*2+g
        const float* __restrict__ gnw,         // (64) [g*32+o]
        const float* __restrict__ gnb,
        float* __restrict__ out) {
    __shared__ float swsh[NF * NF];
    __shared__ float xn_sh[8][64];

    for (int i = threadIdx.x; i < NF * NF; i += 256)
        swsh[i] = selfw[(i & 31) * NF + (i >> 5)];
    __syncthreads();

    int warp = threadIdx.x >> 5;
    int lane = threadIdx.x & 31;
    int a = blockIdx.x * 8 + warp;

    // segment search: lanes 0/1
    int target = a + (lane & 1);
    int lo = 0, hi = N_PAIRS;
    while (lo < hi) {
        int mid = (lo + hi) >> 1;
        if (pair_first[mid] < target) lo = mid + 1; else hi = mid;
    }
    int p0 = __shfl_sync(0xffffffffu, lo, 0);
    int p1 = __shfl_sync(0xffffffffu, lo, 1);

    float tf0 = 0.f, tf1 = 0.f, tf2 = 0.f, tf3 = 0.f;
    int p = p0;
    for (; p + 1 < p1; p += 2) {
        float ha = __half2float(g_hh[p * NF + lane]);
        float hb = __half2float(g_hh[(p + 1) * NF + lane]);
        const float4 ra = *reinterpret_cast<const float4*>(rhat + p * NC);
        const float4 rb = *reinterpret_cast<const float4*>(rhat + (p + 1) * NC);
        tf0 = fmaf(ra.x, ha, tf0); tf0 = fmaf(rb.x, hb, tf0);
        tf1 = fmaf(ra.y, ha, tf1); tf1 = fmaf(rb.y, hb, tf1);
        tf2 = fmaf(ra.z, ha, tf2); tf2 = fmaf(rb.z, hb, tf2);
        tf3 = fmaf(ra.w, ha, tf3); tf3 = fmaf(rb.w, hb, tf3);
    }
    if (p < p1) {
        float ha = __half2float(g_hh[p * NF + lane]);
        const float4 ra = *reinterpret_cast<const float4*>(rhat + p * NC);
        tf0 = fmaf(ra.x, ha, tf0);
        tf1 = fmaf(ra.y, ha, tf1);
        tf2 = fmaf(ra.z, ha, tf2);
        tf3 = fmaf(ra.w, ha, tf3);
    }

    // invariants
    float inv0 = tf0;
    float inv1 = tf1 * tf1 + tf2 * tf2 + tf3 * tf3;

    // GroupNorm across lanes
    float xn0, xn1;
    {
        float s = inv0, sq = inv0 * inv0;
#pragma unroll
        for (int m = 16; m; m >>= 1) {
            s  += __shfl_xor_sync(0xffffffffu, s,  m);
            sq += __shfl_xor_sync(0xffffffffu, sq, m);
        }
        float mean = s * (1.0f / 32.0f);
        float var  = sq * (1.0f / 32.0f) - mean * mean;
        xn0 = (inv0 - mean) * rsqrtf(var + GN_EPS) * gnw[lane] + gnb[lane];
    }
    {
        float s = inv1, sq = inv1 * inv1;
#pragma unroll
        for (int m = 16; m; m >>= 1) {
            s  += __shfl_xor_sync(0xffffffffu, s,  m);
            sq += __shfl_xor_sync(0xffffffffu, sq, m);
        }
        float mean = s * (1.0f / 32.0f);
        float var  = sq * (1.0f / 32.0f) - mean * mean;
        xn1 = (inv1 - mean) * rsqrtf(var + GN_EPS) * gnw[NF + lane] + gnb[NF + lane];
    }
    xn_sh[warp][lane * 2 + 0] = xn0;   // k = o*2 + g
    xn_sh[warp][lane * 2 + 1] = xn1;
    __syncwarp();

    float m = 0.f;
#pragma unroll
    for (int k = 0; k < 2 * NF; k++)
        m = fmaf(xn_sh[warp][k], mixw[k * NF + lane], m);

    float sp = selfb[lane];
    const float* fa = feat + a * NF;
#pragma unroll
    for (int f = 0; f < NF; f++)
        sp = fmaf(fa[f], swsh[f * NF + lane], sp);

    out[a * NF + lane] = m + sp;
}

// ---------------- launch ----------------------------------------------------
extern "C" void kernel_launch(void* const* d_in, const int* in_sizes, int n_in,
                              void* d_out, int out_size) {
    const float* in_features    = (const float*)d_in[0];
    const float* tensor_rhats   = (const float*)d_in[1];
    const float* dist_pairs     = (const float*)d_in[2];
    const float* int_weights    = (const float*)d_in[3];
    const float* selfint_w      = (const float*)d_in[4];
    const float* selfint_b      = (const float*)d_in[5];
    const float* mixing_weights = (const float*)d_in[6];
    const float* gn_weight      = (const float*)d_in[7];
    const float* gn_bias        = (const float*)d_in[8];
    const float* sens_mu        = (const float*)d_in[9];
    const float* sens_sigma     = (const float*)d_in[10];
    const int*   pair_first     = (const int*)d_in[11];
    const int*   pair_second    = (const int*)d_in[12];
    float* out = (float*)d_out;

    proj_kernel<<<N_ATOMS / APB, 512>>>(in_features, int_weights);
    hpair_kernel<<<N_PAIRS / 8, 256>>>(dist_pairs, sens_mu, sens_sigma, pair_second);
    atom_kernel<<<N_ATOMS / 8, 256>>>(in_features, tensor_rhats, pair_first,
                                      selfint_w, selfint_b, mixing_weights,
                                      gn_weight, gn_bias, out);
}